// round 16
// baseline (speedup 1.0000x reference)
#include <cuda_runtime.h>
#include <cuda_bf16.h>
#include <cstdint>

#define BDIM 256
#define FDIM 4
#define MDIM 256
#define DDIM 8192
#define WDIM 256          // DDIM/32 packed words
#define NITERS 10

// Scratch (device globals -- allocation is forbidden)
__device__ float g_sim0[BDIM * FDIM * MDIM];      // 1 MB sim buffer (even stages, stage0, final)
__device__ float g_sim1[BDIM * FDIM * MDIM];      // 1 MB sim buffer (odd stages)
__device__ float g_colsum[FDIM * DDIM];
__device__ float g_P[FDIM * DDIM];
__device__ unsigned g_eS[BDIM * FDIM * WDIM];     // packed est sign bits
__device__ unsigned g_eM[BDIM * FDIM * WDIM];     // packed est nonzero mask
__device__ unsigned g_iS[BDIM * WDIM];            // packed inp sign bits
__device__ unsigned g_cbSt[FDIM * WDIM * MDIM];   // cb sign bits transposed [f][w][m]
__device__ __nv_bfloat16 g_cbB[(size_t)FDIM * DDIM * 256]; // cb transposed [f][d][m] bf16
__device__ int g_done;
__device__ int g_diff;
__device__ int g_k;
__device__ unsigned g_ticket;

// ---------------------------------------------------------------------------
// ONE setup kernel: colsum+P+zero both sims+flags (32), cb signs (32768),
// inp signs (8192), cb bf16 transpose (1024).  grid = 42016.
// ---------------------------------------------------------------------------
__global__ void setup_kernel(const float* __restrict__ cb,
                             const float* __restrict__ inp) {
    __shared__ signed char t[32][260];
    int bx = blockIdx.x;
    if (bx < 32) {
        int d = bx * 256 + threadIdx.x;
        float s[4];
        #pragma unroll
        for (int f = 0; f < 4; f++) {
            const float* p = cb + ((size_t)f * MDIM) * DDIM + d;
            float acc = 0.f;
            for (int m = 0; m < MDIM; m++) acc += p[(size_t)m * DDIM];
            s[f] = acc;
            g_colsum[f * DDIM + d] = acc;
        }
        g_P[d]            = (s[1] * s[2]) * s[3];
        g_P[DDIM + d]     = (s[0] * s[2]) * s[3];
        g_P[2 * DDIM + d] = (s[0] * s[1]) * s[3];
        g_P[3 * DDIM + d] = (s[0] * s[1]) * s[2];
        for (int i = d; i < BDIM * FDIM * MDIM; i += 32 * 256) {
            g_sim0[i] = 0.f;
            g_sim1[i] = 0.f;
        }
        if (d == 0) { g_done = 0; g_diff = 0; g_k = 0; g_ticket = 0; }
    } else if (bx < 32 + 32768) {
        int idx = (bx - 32) * 256 + threadIdx.x;       // (f*M+m)*8192 + d
        float v = cb[idx];
        unsigned neg = __ballot_sync(0xffffffffu, v < 0.f);
        if ((threadIdx.x & 31) == 0) {
            int fm = idx >> 13;
            int d = idx & (DDIM - 1);
            g_cbSt[((size_t)(fm >> 8) * WDIM + (d >> 5)) * MDIM + (fm & 255)] = neg;
        }
    } else if (bx < 32 + 32768 + 8192) {
        int idx = (bx - 32800) * 256 + threadIdx.x;    // b*8192 + d
        unsigned neg = __ballot_sync(0xffffffffu, inp[idx] < 0.f);
        if ((threadIdx.x & 31) == 0) {
            int b = idx >> 13;
            int d = idx & (DDIM - 1);
            g_iS[(size_t)b * WDIM + (d >> 5)] = neg;
        }
    } else {
        int pb = bx - 40992;                           // 0..1023: (dblock, f)
        int d0 = (pb >> 2) * 32;
        int f = pb & 3;
        for (int idx = threadIdx.x; idx < 256 * 32; idx += 256) {
            int m = idx >> 5;
            int dl = idx & 31;
            t[dl][m] = (signed char)cb[((size_t)f * MDIM + m) * DDIM + d0 + dl];
        }
        __syncthreads();
        for (int idx = threadIdx.x; idx < 32 * 256; idx += 256) {
            int dl = idx >> 8;
            int m = idx & 255;
            g_cbB[((size_t)f * DDIM + d0 + dl) * 256 + m] =
                __float2bfloat16((float)t[dl][m]);
        }
    }
}

// ---------------------------------------------------------------------------
__device__ __forceinline__ void last_block_step(int ldiff, int nblocks) {
    int any = __syncthreads_or(ldiff);
    if (threadIdx.x == 0) {
        if (any) atomicOr(&g_diff, 1);
        __threadfence();
        unsigned tk = atomicAdd(&g_ticket, 1u);
        if (tk == (unsigned)(nblocks - 1)) {
            g_ticket = 0;
            g_k = g_k + 1;
            if (atomicAdd(&g_diff, 0) == 0) g_done = 1;
            g_diff = 0;
        }
    }
}

// ---------------------------------------------------------------------------
// stage-0 GEMM1 (float, split-K=16 atomicAdd into g_sim0), A = inp*P on the fly
// grid (16, 4, 16) = 1024 blocks.
// ---------------------------------------------------------------------------
__global__ void gemm1_f32_kernel(const float* __restrict__ cb,
                                 const float* __restrict__ inp) {
    if (g_done) return;
    int bt = blockIdx.x >> 2;
    int mt = blockIdx.x & 3;
    int f = blockIdx.y;
    int b0 = bt * 64;
    int m0 = mt * 64;
    int k0 = blockIdx.z * (DDIM / 16);     // 512 per z-slice

    __shared__ __align__(16) float As[32][68];
    __shared__ __align__(16) float Bs[32][68];

    int tx = threadIdx.x & 15;
    int ty = threadIdx.x >> 4;

    float acc[4][4];
    for (int i = 0; i < 4; i++)
        for (int j = 0; j < 4; j++) acc[i][j] = 0.f;

    for (int kk = 0; kk < DDIM / 16; kk += 32) {
        for (int e = threadIdx.x; e < 2048; e += 256) {
            int r = e >> 5;
            int c = e & 31;
            int d = k0 + kk + c;
            As[c][r] = inp[(size_t)(b0 + r) * DDIM + d] * g_P[(size_t)f * DDIM + d];
            Bs[c][r] = cb[((size_t)f * MDIM + m0 + r) * DDIM + d];
        }
        __syncthreads();
        #pragma unroll
        for (int k = 0; k < 32; k++) {
            float4 av = *(const float4*)&As[k][tx * 4];
            float4 bv = *(const float4*)&Bs[k][ty * 4];
            acc[0][0] += av.x * bv.x; acc[0][1] += av.x * bv.y; acc[0][2] += av.x * bv.z; acc[0][3] += av.x * bv.w;
            acc[1][0] += av.y * bv.x; acc[1][1] += av.y * bv.y; acc[1][2] += av.y * bv.z; acc[1][3] += av.y * bv.w;
            acc[2][0] += av.z * bv.x; acc[2][1] += av.z * bv.y; acc[2][2] += av.z * bv.z; acc[2][3] += av.z * bv.w;
            acc[3][0] += av.w * bv.x; acc[3][1] += av.w * bv.y; acc[3][2] += av.w * bv.z; acc[3][3] += av.w * bv.w;
        }
        __syncthreads();
    }
    for (int i = 0; i < 4; i++)
        for (int j = 0; j < 4; j++) {
            int b = b0 + tx * 4 + i;
            int m = m0 + ty * 4 + j;
            atomicAdd(&g_sim0[((size_t)b * FDIM + f) * MDIM + m], acc[i][j]);
        }
}

// ---------------------------------------------------------------------------
// stage-0 GEMM2 (float): reads g_sim0, sign + convergence (vs colsum) +
// PACKED est + zeroes g_sim1 (for stage 1) + step.
// ---------------------------------------------------------------------------
__global__ void gemm2_f32_kernel(const float* __restrict__ cb) {
    if (g_done) return;
    int f = blockIdx.z;
    int b0 = blockIdx.y * 64;
    int d0 = blockIdx.x * 64;

    // zero next-stage buffer slice: 2048 blocks x 32 float4 = 65536 float4 exactly
    {
        int flat = (blockIdx.z * gridDim.y + blockIdx.y) * gridDim.x + blockIdx.x; // < 2048
        if (threadIdx.x < 32)
            ((float4*)g_sim1)[flat * 32 + threadIdx.x] = make_float4(0.f, 0.f, 0.f, 0.f);
    }

    __shared__ __align__(16) float As[32][68];
    __shared__ __align__(16) float Bs[32][68];
    __shared__ unsigned char nibS[64][16];
    __shared__ unsigned char nibM[64][16];

    int tx = threadIdx.x & 15;
    int ty = threadIdx.x >> 4;

    float acc[4][4];
    for (int i = 0; i < 4; i++)
        for (int j = 0; j < 4; j++) acc[i][j] = 0.f;

    for (int mb = 0; mb < MDIM; mb += 32) {
        for (int e = threadIdx.x; e < 2048; e += 256) {
            int r = e >> 5;
            int c = e & 31;
            As[c][r] = g_sim0[((size_t)(b0 + r) * FDIM + f) * MDIM + mb + c];
        }
        for (int e = threadIdx.x; e < 2048; e += 256) {
            int m = e >> 6;
            int dd = e & 63;
            Bs[m][dd] = cb[((size_t)f * MDIM + mb + m) * DDIM + d0 + dd];
        }
        __syncthreads();
        #pragma unroll
        for (int m = 0; m < 32; m++) {
            float4 av = *(const float4*)&As[m][ty * 4];
            float4 bv = *(const float4*)&Bs[m][tx * 4];
            acc[0][0] += av.x * bv.x; acc[0][1] += av.x * bv.y; acc[0][2] += av.x * bv.z; acc[0][3] += av.x * bv.w;
            acc[1][0] += av.y * bv.x; acc[1][1] += av.y * bv.y; acc[1][2] += av.y * bv.z; acc[1][3] += av.y * bv.w;
            acc[2][0] += av.z * bv.x; acc[2][1] += av.z * bv.y; acc[2][2] += av.z * bv.z; acc[2][3] += av.z * bv.w;
            acc[3][0] += av.w * bv.x; acc[3][1] += av.w * bv.y; acc[3][2] += av.w * bv.z; acc[3][3] += av.w * bv.w;
        }
        __syncthreads();
    }

    int ldiff = 0;
    #pragma unroll
    for (int i = 0; i < 4; i++) {
        unsigned sn = 0, mn = 0;
        #pragma unroll
        for (int j = 0; j < 4; j++) {
            float v = acc[i][j];
            float s = (v > 0.f) ? 1.f : ((v < 0.f) ? -1.f : 0.f);
            int d = d0 + tx * 4 + j;
            if (s != g_colsum[(size_t)f * DDIM + d]) ldiff = 1;
            if (v < 0.f) sn |= (1u << j);
            if (v != 0.f) mn |= (1u << j);
        }
        nibS[ty * 4 + i][tx] = (unsigned char)sn;
        nibM[ty * 4 + i][tx] = (unsigned char)mn;
    }
    __syncthreads();

    int t = threadIdx.x;
    if (t < 128) {
        int bl = t >> 1;
        int wsel = t & 1;
        unsigned ws = 0, wm = 0;
        #pragma unroll
        for (int n = 0; n < 8; n++) {
            ws |= (unsigned)nibS[bl][wsel * 8 + n] << (4 * n);
            wm |= (unsigned)nibM[bl][wsel * 8 + n] << (4 * n);
        }
        size_t o = ((size_t)(b0 + bl) * FDIM + f) * WDIM + (d0 >> 5) + wsel;
        g_eS[o] = ws;
        g_eM[o] = wm;
    }
    last_block_step(ldiff, 2048);
}

// ---------------------------------------------------------------------------
// iteration GEMM1: split-K packed popc with fused newest.
// grid (8 btiles(32), 8 mtiles(32), F*4 kslices) = 1024 blocks, 256 thr.
// Each block covers K-slice of 64 words; partial sims atomicAdd (exact ints).
// ---------------------------------------------------------------------------
__global__ void gemm1_split_kernel(int parity) {
    if (g_done) return;
    float* simBuf = parity ? g_sim1 : g_sim0;
    int b0 = blockIdx.x * 32;
    int m0 = blockIdx.y * 32;
    int f = blockIdx.z >> 2;
    int ks = blockIdx.z & 3;
    int wbase = ks * 64;
    int f1 = (f + 1) & 3, f2 = (f + 2) & 3, f3 = (f + 3) & 3;

    __shared__ unsigned AS[32][33];
    __shared__ unsigned AM[32][33];
    __shared__ unsigned BS[32][33];

    int tx = threadIdx.x & 15;
    int ty = threadIdx.x >> 4;

    int acc[2][2] = {{0, 0}, {0, 0}};
    int accM[2] = {0, 0};

    for (int w0 = wbase; w0 < wbase + 64; w0 += 32) {
        for (int e = threadIdx.x; e < 1024; e += 256) {
            int r = e >> 5;
            int c = e & 31;
            int b = b0 + r;
            int w = w0 + c;
            size_t base = ((size_t)b * FDIM) * WDIM + w;
            unsigned so1 = g_eS[base + (size_t)f1 * WDIM];
            unsigned so2 = g_eS[base + (size_t)f2 * WDIM];
            unsigned so3 = g_eS[base + (size_t)f3 * WDIM];
            unsigned mo1 = g_eM[base + (size_t)f1 * WDIM];
            unsigned mo2 = g_eM[base + (size_t)f2 * WDIM];
            unsigned mo3 = g_eM[base + (size_t)f3 * WDIM];
            unsigned Mf = mo1 & mo2 & mo3;
            unsigned Sf = (g_iS[(size_t)b * WDIM + w] ^ so1 ^ so2 ^ so3) & Mf;
            AS[c][r] = Sf;
            AM[c][r] = Mf;
        }
        for (int e = threadIdx.x; e < 1024; e += 256) {
            int w = e >> 5;
            int m = e & 31;
            BS[w][m] = g_cbSt[((size_t)f * WDIM + w0 + w) * MDIM + m0 + m];
        }
        __syncthreads();
        #pragma unroll
        for (int w = 0; w < 32; w++) {
            unsigned sa0 = AS[w][tx * 2 + 0];
            unsigned sa1 = AS[w][tx * 2 + 1];
            unsigned ma0 = AM[w][tx * 2 + 0];
            unsigned ma1 = AM[w][tx * 2 + 1];
            unsigned sb0 = BS[w][ty * 2 + 0];
            unsigned sb1 = BS[w][ty * 2 + 1];
            accM[0] += __popc(ma0);
            accM[1] += __popc(ma1);
            acc[0][0] += __popc((sa0 ^ sb0) & ma0);
            acc[0][1] += __popc((sa0 ^ sb1) & ma0);
            acc[1][0] += __popc((sa1 ^ sb0) & ma1);
            acc[1][1] += __popc((sa1 ^ sb1) & ma1);
        }
        __syncthreads();
    }

    #pragma unroll
    for (int i = 0; i < 2; i++) {
        int b = b0 + tx * 2 + i;
        #pragma unroll
        for (int j = 0; j < 2; j++) {
            int m = m0 + ty * 2 + j;
            atomicAdd(&simBuf[((size_t)b * FDIM + f) * MDIM + m],
                      (float)(accM[i] - 2 * acc[i][j]));
        }
    }
}

// ---------------------------------------------------------------------------
// final GEMM1: full-K packed popc from est planes; writes g_sim0 directly.
// grid (8, 8, F) = 256 blocks.
// ---------------------------------------------------------------------------
__global__ void gemm1_final_kernel() {
    int b0 = blockIdx.x * 32;
    int m0 = blockIdx.y * 32;
    int f = blockIdx.z;

    __shared__ unsigned AS[32][33];
    __shared__ unsigned AM[32][33];
    __shared__ unsigned BS[32][33];

    int tx = threadIdx.x & 15;
    int ty = threadIdx.x >> 4;

    int acc[2][2] = {{0, 0}, {0, 0}};
    int accM[2] = {0, 0};

    for (int w0 = 0; w0 < WDIM; w0 += 32) {
        for (int e = threadIdx.x; e < 1024; e += 256) {
            int r = e >> 5;
            int c = e & 31;
            size_t src = ((size_t)(b0 + r) * FDIM + f) * WDIM + w0 + c;
            AS[c][r] = g_eS[src];
            AM[c][r] = g_eM[src];
        }
        for (int e = threadIdx.x; e < 1024; e += 256) {
            int w = e >> 5;
            int m = e & 31;
            BS[w][m] = g_cbSt[((size_t)f * WDIM + w0 + w) * MDIM + m0 + m];
        }
        __syncthreads();
        #pragma unroll
        for (int w = 0; w < 32; w++) {
            unsigned sa0 = AS[w][tx * 2 + 0];
            unsigned sa1 = AS[w][tx * 2 + 1];
            unsigned ma0 = AM[w][tx * 2 + 0];
            unsigned ma1 = AM[w][tx * 2 + 1];
            unsigned sb0 = BS[w][ty * 2 + 0];
            unsigned sb1 = BS[w][ty * 2 + 1];
            accM[0] += __popc(ma0);
            accM[1] += __popc(ma1);
            acc[0][0] += __popc((sa0 ^ sb0) & ma0);
            acc[0][1] += __popc((sa0 ^ sb1) & ma0);
            acc[1][0] += __popc((sa1 ^ sb0) & ma1);
            acc[1][1] += __popc((sa1 ^ sb1) & ma1);
        }
        __syncthreads();
    }

    #pragma unroll
    for (int i = 0; i < 2; i++) {
        int b = b0 + tx * 2 + i;
        #pragma unroll
        for (int j = 0; j < 2; j++) {
            int m = m0 + ty * 2 + j;
            g_sim0[((size_t)b * FDIM + f) * MDIM + m] = (float)(accM[i] - 2 * acc[i][j]);
        }
    }
}

// ---------------------------------------------------------------------------
// iteration GEMM2 via bf16 mma.sync.m16n8k16 (fused K=512 lo|hi planes, built
// inline from f32 sim).  Reads sim[parity], zeroes sim[parity^1] for next stage.
// Block: 128 b x 64 d, f fixed.  grid (128, 2, F) = 1024 blocks, 256 thr.
// Exact: lo in [-64,63], hi<<7 multiples of 128 <= 8192 -- both exact bf16;
// f32 accumulation of integers < 2^21 exact.
// ---------------------------------------------------------------------------
__device__ __forceinline__ void hmma16816(float& c0, float& c1, float& c2, float& c3,
                                          unsigned a0, unsigned a1, unsigned a2, unsigned a3,
                                          unsigned b0, unsigned b1) {
    asm volatile(
        "mma.sync.aligned.m16n8k16.row.col.f32.bf16.bf16.f32 "
        "{%0,%1,%2,%3}, {%4,%5,%6,%7}, {%8,%9}, {%0,%1,%2,%3};\n"
        : "+f"(c0), "+f"(c1), "+f"(c2), "+f"(c3)
        : "r"(a0), "r"(a1), "r"(a2), "r"(a3), "r"(b0), "r"(b1));
}

__global__ void gemm2_bf16_kernel(int parity) {
    if (g_done) return;
    const float* simBuf = parity ? g_sim1 : g_sim0;
    float* zeroBuf = parity ? g_sim0 : g_sim1;

    // zero next-stage buffer slice: 1024 blocks x 64 float4 = 65536 float4 exactly
    {
        int flat = (blockIdx.z * gridDim.y + blockIdx.y) * gridDim.x + blockIdx.x; // < 1024
        if (threadIdx.x < 64)
            ((float4*)zeroBuf)[flat * 64 + threadIdx.x] = make_float4(0.f, 0.f, 0.f, 0.f);
    }

    __shared__ __align__(16) unsigned sA[128 * 36];   // 128 rows x (32 data + 4 pad)
    __shared__ __align__(16) unsigned sB[64 * 36];
    __shared__ unsigned char sSM[128][64];

    int f = blockIdx.z;
    int d0 = blockIdx.x * 64;
    int b0 = blockIdx.y * 128;
    int tid = threadIdx.x;
    int wid = tid >> 5;
    int lane = tid & 31;
    int g = lane >> 2;
    int tig = lane & 3;
    int wb = wid & 3;     // 32 b-rows
    int wd = wid >> 2;    // 0..1: 32 d-cols

    float acc[2][4][4];
    #pragma unroll
    for (int mt = 0; mt < 2; mt++)
        #pragma unroll
        for (int nt = 0; nt < 4; nt++)
            #pragma unroll
            for (int i = 0; i < 4; i++) acc[mt][nt][i] = 0.f;

    const uint4* B4 = (const uint4*)g_cbB;    // 32 uint4 per (f,d) row
    uint4* sB4 = (uint4*)sB;

    for (int kc = 0; kc < 8; kc++) {
        // stage A chunk from f32 sim: chunk kc<4 -> lo plane, kc>=4 -> hi<<7
        for (int i = tid; i < 4096; i += 256) {
            int row = i >> 5;                 // 0..127
            int p = i & 31;                   // u32 within row
            int mb = (kc & 3) * 64 + p * 2;
            const float* srow = simBuf + ((size_t)(b0 + row) * FDIM + f) * MDIM;
            int s0 = (int)srow[mb];
            int s1 = (int)srow[mb + 1];
            int h0 = (s0 + 64) >> 7;
            int h1 = (s1 + 64) >> 7;
            int x0, x1;
            if (kc < 4) { x0 = s0 - (h0 << 7); x1 = s1 - (h1 << 7); }
            else        { x0 = h0 << 7;        x1 = h1 << 7; }
            unsigned v = (unsigned)__bfloat16_as_ushort(__float2bfloat16((float)x0))
                       | ((unsigned)__bfloat16_as_ushort(__float2bfloat16((float)x1)) << 16);
            sA[row * 36 + p] = v;
        }
        // stage B chunk: 64 rows x 64 bf16 (fused B = [cb | cb] -> kc&3)
        for (int i = tid; i < 512; i += 256) {
            int row = i >> 3;
            int un = i & 7;
            sB4[row * 9 + un] = B4[((size_t)f * DDIM + d0 + row) * 32 + (kc & 3) * 8 + un];
        }
        __syncthreads();
        #pragma unroll
        for (int s = 0; s < 4; s++) {    // 4 ksteps of 16 within chunk
            unsigned a[2][4];
            #pragma unroll
            for (int mt = 0; mt < 2; mt++) {
                int r = wb * 32 + mt * 16 + g;
                a[mt][0] = sA[r * 36 + s * 8 + tig];
                a[mt][1] = sA[(r + 8) * 36 + s * 8 + tig];
                a[mt][2] = sA[r * 36 + s * 8 + tig + 4];
                a[mt][3] = sA[(r + 8) * 36 + s * 8 + tig + 4];
            }
            #pragma unroll
            for (int nt = 0; nt < 4; nt++) {
                int rd = wd * 32 + nt * 8 + g;
                unsigned bb0 = sB[rd * 36 + s * 8 + tig];
                unsigned bb1 = sB[rd * 36 + s * 8 + tig + 4];
                #pragma unroll
                for (int mt = 0; mt < 2; mt++)
                    hmma16816(acc[mt][nt][0], acc[mt][nt][1], acc[mt][nt][2], acc[mt][nt][3],
                              a[mt][0], a[mt][1], a[mt][2], a[mt][3], bb0, bb1);
            }
        }
        __syncthreads();
    }

    // epilogue (values exact integers in f32)
    #pragma unroll
    for (int mt = 0; mt < 2; mt++) {
        int r0 = wb * 32 + mt * 16 + g;
        #pragma unroll
        for (int nt = 0; nt < 4; nt++) {
            int c0 = wd * 32 + nt * 8 + tig * 2;
            float v0 = acc[mt][nt][0];
            float v1 = acc[mt][nt][1];
            float v2 = acc[mt][nt][2];
            float v3 = acc[mt][nt][3];
            sSM[r0][c0]         = (unsigned char)((v0 < 0.f ? 1u : 0u) | (v0 != 0.f ? 2u : 0u));
            sSM[r0][c0 + 1]     = (unsigned char)((v1 < 0.f ? 1u : 0u) | (v1 != 0.f ? 2u : 0u));
            sSM[r0 + 8][c0]     = (unsigned char)((v2 < 0.f ? 1u : 0u) | (v2 != 0.f ? 2u : 0u));
            sSM[r0 + 8][c0 + 1] = (unsigned char)((v3 < 0.f ? 1u : 0u) | (v3 != 0.f ? 2u : 0u));
        }
    }
    __syncthreads();

    int ldiff = 0;
    {
        int row = tid >> 1;          // 0..127
        int wsel = tid & 1;
        unsigned ws = 0, wm = 0;
        #pragma unroll
        for (int n = 0; n < 32; n++) {
            unsigned byte = sSM[row][wsel * 32 + n];
            ws |= (byte & 1u) << n;
            wm |= ((byte >> 1) & 1u) << n;
        }
        size_t o = ((size_t)(b0 + row) * FDIM + f) * WDIM + (d0 >> 5) + wsel;
        if (ws != g_eS[o] || wm != g_eM[o]) ldiff = 1;
        g_eS[o] = ws;
        g_eM[o] = wm;
    }
    last_block_step(ldiff, 1024);
}

// ---------------------------------------------------------------------------
// argmax over m (first-index tie-break) + write k.  Reads g_sim0.
// ---------------------------------------------------------------------------
__global__ void argmax_kernel(float* __restrict__ out, int out_size) {
    int gtid = blockIdx.x * blockDim.x + threadIdx.x;
    int w = gtid >> 5;
    int lane = gtid & 31;
    if (w < BDIM * FDIM) {
        const float* srow = g_sim0 + (size_t)w * MDIM;
        float bv = -3.0e38f;
        int bi = 0;
        for (int m = lane; m < MDIM; m += 32) {
            float v = srow[m];
            if (v > bv) { bv = v; bi = m; }
        }
        for (int off = 16; off > 0; off >>= 1) {
            float ov = __shfl_down_sync(0xffffffffu, bv, off);
            int oi = __shfl_down_sync(0xffffffffu, bi, off);
            if (ov > bv || (ov == bv && oi < bi)) { bv = ov; bi = oi; }
        }
        if (lane == 0) out[w] = (float)bi;
    }
    if (gtid == 0 && out_size > BDIM * FDIM) out[BDIM * FDIM] = (float)g_k;
}

// ---------------------------------------------------------------------------
extern "C" void kernel_launch(void* const* d_in, const int* in_sizes, int n_in,
                              void* d_out, int out_size) {
    const float* inp;
    const float* cb;
    if (in_sizes[0] < in_sizes[1]) { inp = (const float*)d_in[0]; cb = (const float*)d_in[1]; }
    else                           { inp = (const float*)d_in[1]; cb = (const float*)d_in[0]; }
    float* out = (float*)d_out;

    // launch #0..#3: setup, g1f32, g2f32, g1split (ncu capture = index 3)
    setup_kernel<<<42016, 256>>>(cb, inp);
    gemm1_f32_kernel<<<dim3(16, FDIM, 16), 256>>>(cb, inp);
    gemm2_f32_kernel<<<dim3(DDIM / 64, BDIM / 64, FDIM), 256>>>(cb);

    for (int it = 1; it < NITERS; it++) {
        int parity = it & 1;
        gemm1_split_kernel<<<dim3(8, 8, FDIM * 4), 256>>>(parity);
        gemm2_bf16_kernel<<<dim3(DDIM / 64, BDIM / 128, FDIM), 256>>>(parity);
    }

    gemm1_final_kernel<<<dim3(8, 8, FDIM), 256>>>();
    argmax_kernel<<<(BDIM * FDIM * 32) / 256, 256>>>(out, out_size);
}

// round 17
// speedup vs baseline: 1.0962x; 1.0962x over previous
#include <cuda_runtime.h>
#include <cuda_bf16.h>
#include <cstdint>

#define BDIM 256
#define FDIM 4
#define MDIM 256
#define DDIM 8192
#define WDIM 256          // DDIM/32 packed words
#define NITERS 10

// Scratch (device globals -- allocation is forbidden)
__device__ float g_sim[BDIM * FDIM * MDIM];       // 1 MB (stage0 + final argmax)
__device__ float g_colsum[FDIM * DDIM];
__device__ float g_P[FDIM * DDIM];
__device__ unsigned g_eS[BDIM * FDIM * WDIM];     // packed est sign bits
__device__ unsigned g_eM[BDIM * FDIM * WDIM];     // packed est nonzero mask
__device__ unsigned g_iS[BDIM * WDIM];            // packed inp sign bits
__device__ unsigned g_cbSt[FDIM * WDIM * MDIM];   // cb sign bits transposed [f][w][m]
__device__ __nv_bfloat16 g_simB[BDIM * FDIM * 512];        // A planes: [lo(256) | 128*hi(256)]
__device__ __nv_bfloat16 g_cbB[(size_t)FDIM * DDIM * 256]; // cb transposed [f][d][m] bf16
__device__ int g_done;
__device__ int g_diff;
__device__ int g_k;
__device__ unsigned g_ticket;

// ---------------------------------------------------------------------------
// ONE setup kernel: colsum+P+zero sim+flags (32), cb signs (32768),
// inp signs (8192), cb bf16 transpose (1024).  grid = 42016.
// ---------------------------------------------------------------------------
__global__ void setup_kernel(const float* __restrict__ cb,
                             const float* __restrict__ inp) {
    __shared__ signed char t[32][260];
    int bx = blockIdx.x;
    if (bx < 32) {
        int d = bx * 256 + threadIdx.x;
        float s[4];
        #pragma unroll
        for (int f = 0; f < 4; f++) {
            const float* p = cb + ((size_t)f * MDIM) * DDIM + d;
            float acc = 0.f;
            for (int m = 0; m < MDIM; m++) acc += p[(size_t)m * DDIM];
            s[f] = acc;
            g_colsum[f * DDIM + d] = acc;
        }
        g_P[d]            = (s[1] * s[2]) * s[3];
        g_P[DDIM + d]     = (s[0] * s[2]) * s[3];
        g_P[2 * DDIM + d] = (s[0] * s[1]) * s[3];
        g_P[3 * DDIM + d] = (s[0] * s[1]) * s[2];
        for (int i = d; i < BDIM * FDIM * MDIM; i += 32 * 256) g_sim[i] = 0.f;
        if (d == 0) { g_done = 0; g_diff = 0; g_k = 0; g_ticket = 0; }
    } else if (bx < 32 + 32768) {
        int idx = (bx - 32) * 256 + threadIdx.x;       // (f*M+m)*8192 + d
        float v = cb[idx];
        unsigned neg = __ballot_sync(0xffffffffu, v < 0.f);
        if ((threadIdx.x & 31) == 0) {
            int fm = idx >> 13;
            int d = idx & (DDIM - 1);
            g_cbSt[((size_t)(fm >> 8) * WDIM + (d >> 5)) * MDIM + (fm & 255)] = neg;
        }
    } else if (bx < 32 + 32768 + 8192) {
        int idx = (bx - 32800) * 256 + threadIdx.x;    // b*8192 + d
        unsigned neg = __ballot_sync(0xffffffffu, inp[idx] < 0.f);
        if ((threadIdx.x & 31) == 0) {
            int b = idx >> 13;
            int d = idx & (DDIM - 1);
            g_iS[(size_t)b * WDIM + (d >> 5)] = neg;
        }
    } else {
        int pb = bx - 40992;                           // 0..1023: (dblock, f)
        int d0 = (pb >> 2) * 32;
        int f = pb & 3;
        for (int idx = threadIdx.x; idx < 256 * 32; idx += 256) {
            int m = idx >> 5;
            int dl = idx & 31;
            t[dl][m] = (signed char)cb[((size_t)f * MDIM + m) * DDIM + d0 + dl];
        }
        __syncthreads();
        for (int idx = threadIdx.x; idx < 32 * 256; idx += 256) {
            int dl = idx >> 8;
            int m = idx & 255;
            g_cbB[((size_t)f * DDIM + d0 + dl) * 256 + m] =
                __float2bfloat16((float)t[dl][m]);
        }
    }
}

// ---------------------------------------------------------------------------
__device__ __forceinline__ void last_block_step(int ldiff, int nblocks) {
    int any = __syncthreads_or(ldiff);
    if (threadIdx.x == 0) {
        if (any) atomicOr(&g_diff, 1);
        __threadfence();
        unsigned tk = atomicAdd(&g_ticket, 1u);
        if (tk == (unsigned)(nblocks - 1)) {
            g_ticket = 0;
            g_k = g_k + 1;
            if (atomicAdd(&g_diff, 0) == 0) g_done = 1;
            g_diff = 0;
        }
    }
}

// ---------------------------------------------------------------------------
// stage-0 GEMM1 (float, split-K=16 atomicAdd), A = inp*P on the fly.
// grid (16, 4, 16) = 1024 blocks.  Exact: integers < 2^27.
// ---------------------------------------------------------------------------
__global__ void gemm1_f32_kernel(const float* __restrict__ cb,
                                 const float* __restrict__ inp) {
    if (g_done) return;
    int bt = blockIdx.x >> 2;
    int mt = blockIdx.x & 3;
    int f = blockIdx.y;
    int b0 = bt * 64;
    int m0 = mt * 64;
    int k0 = blockIdx.z * (DDIM / 16);     // 512 per z-slice

    __shared__ __align__(16) float As[32][68];
    __shared__ __align__(16) float Bs[32][68];

    int tx = threadIdx.x & 15;
    int ty = threadIdx.x >> 4;

    float acc[4][4];
    for (int i = 0; i < 4; i++)
        for (int j = 0; j < 4; j++) acc[i][j] = 0.f;

    for (int kk = 0; kk < DDIM / 16; kk += 32) {
        for (int e = threadIdx.x; e < 2048; e += 256) {
            int r = e >> 5;
            int c = e & 31;
            int d = k0 + kk + c;
            As[c][r] = inp[(size_t)(b0 + r) * DDIM + d] * g_P[(size_t)f * DDIM + d];
            Bs[c][r] = cb[((size_t)f * MDIM + m0 + r) * DDIM + d];
        }
        __syncthreads();
        #pragma unroll
        for (int k = 0; k < 32; k++) {
            float4 av = *(const float4*)&As[k][tx * 4];
            float4 bv = *(const float4*)&Bs[k][ty * 4];
            acc[0][0] += av.x * bv.x; acc[0][1] += av.x * bv.y; acc[0][2] += av.x * bv.z; acc[0][3] += av.x * bv.w;
            acc[1][0] += av.y * bv.x; acc[1][1] += av.y * bv.y; acc[1][2] += av.y * bv.z; acc[1][3] += av.y * bv.w;
            acc[2][0] += av.z * bv.x; acc[2][1] += av.z * bv.y; acc[2][2] += av.z * bv.z; acc[2][3] += av.z * bv.w;
            acc[3][0] += av.w * bv.x; acc[3][1] += av.w * bv.y; acc[3][2] += av.w * bv.z; acc[3][3] += av.w * bv.w;
        }
        __syncthreads();
    }
    for (int i = 0; i < 4; i++)
        for (int j = 0; j < 4; j++) {
            int b = b0 + tx * 4 + i;
            int m = m0 + ty * 4 + j;
            atomicAdd(&g_sim[((size_t)b * FDIM + f) * MDIM + m], acc[i][j]);
        }
}

// ---------------------------------------------------------------------------
// stage-0 GEMM2 (float) + sign + convergence (vs colsum) + PACKED est + step.
// ---------------------------------------------------------------------------
__global__ void gemm2_f32_kernel(const float* __restrict__ cb) {
    if (g_done) return;
    int f = blockIdx.z;
    int b0 = blockIdx.y * 64;
    int d0 = blockIdx.x * 64;

    __shared__ __align__(16) float As[32][68];
    __shared__ __align__(16) float Bs[32][68];
    __shared__ unsigned char nibS[64][16];
    __shared__ unsigned char nibM[64][16];

    int tx = threadIdx.x & 15;
    int ty = threadIdx.x >> 4;

    float acc[4][4];
    for (int i = 0; i < 4; i++)
        for (int j = 0; j < 4; j++) acc[i][j] = 0.f;

    for (int mb = 0; mb < MDIM; mb += 32) {
        for (int e = threadIdx.x; e < 2048; e += 256) {
            int r = e >> 5;
            int c = e & 31;
            As[c][r] = g_sim[((size_t)(b0 + r) * FDIM + f) * MDIM + mb + c];
        }
        for (int e = threadIdx.x; e < 2048; e += 256) {
            int m = e >> 6;
            int dd = e & 63;
            Bs[m][dd] = cb[((size_t)f * MDIM + mb + m) * DDIM + d0 + dd];
        }
        __syncthreads();
        #pragma unroll
        for (int m = 0; m < 32; m++) {
            float4 av = *(const float4*)&As[m][ty * 4];
            float4 bv = *(const float4*)&Bs[m][tx * 4];
            acc[0][0] += av.x * bv.x; acc[0][1] += av.x * bv.y; acc[0][2] += av.x * bv.z; acc[0][3] += av.x * bv.w;
            acc[1][0] += av.y * bv.x; acc[1][1] += av.y * bv.y; acc[1][2] += av.y * bv.z; acc[1][3] += av.y * bv.w;
            acc[2][0] += av.z * bv.x; acc[2][1] += av.z * bv.y; acc[2][2] += av.z * bv.z; acc[2][3] += av.z * bv.w;
            acc[3][0] += av.w * bv.x; acc[3][1] += av.w * bv.y; acc[3][2] += av.w * bv.z; acc[3][3] += av.w * bv.w;
        }
        __syncthreads();
    }

    int ldiff = 0;
    #pragma unroll
    for (int i = 0; i < 4; i++) {
        unsigned sn = 0, mn = 0;
        #pragma unroll
        for (int j = 0; j < 4; j++) {
            float v = acc[i][j];
            float s = (v > 0.f) ? 1.f : ((v < 0.f) ? -1.f : 0.f);
            int d = d0 + tx * 4 + j;
            if (s != g_colsum[(size_t)f * DDIM + d]) ldiff = 1;
            if (v < 0.f) sn |= (1u << j);
            if (v != 0.f) mn |= (1u << j);
        }
        nibS[ty * 4 + i][tx] = (unsigned char)sn;
        nibM[ty * 4 + i][tx] = (unsigned char)mn;
    }
    __syncthreads();

    int t = threadIdx.x;
    if (t < 128) {
        int bl = t >> 1;
        int wsel = t & 1;
        unsigned ws = 0, wm = 0;
        #pragma unroll
        for (int n = 0; n < 8; n++) {
            ws |= (unsigned)nibS[bl][wsel * 8 + n] << (4 * n);
            wm |= (unsigned)nibM[bl][wsel * 8 + n] << (4 * n);
        }
        size_t o = ((size_t)(b0 + bl) * FDIM + f) * WDIM + (d0 >> 5) + wsel;
        g_eS[o] = ws;
        g_eM[o] = wm;
    }
    last_block_step(ldiff, 2048);
}

// ---------------------------------------------------------------------------
// packed GEMM1 with FUSED newest (src_est=0) or est source (src_est=1).
// 512 THREADS: half h in {0,1} handles K words [h*128, h*128+128) with its
// own smem buffers; per-half integer sims reduced in smem, half 0 writes.
// src_est=0: writes bf16 A planes [lo | 128*hi].  src_est=1: writes f32 sim.
// grid (8, 8, F) = 256 blocks.
// ---------------------------------------------------------------------------
__global__ void gemm1_packed_kernel(int src_est, int respect_done) {
    if (respect_done && g_done) return;
    int b0 = blockIdx.x * 32;
    int m0 = blockIdx.y * 32;
    int f = blockIdx.z;
    int f1 = (f + 1) & 3, f2 = (f + 2) & 3, f3 = (f + 3) & 3;

    __shared__ unsigned AS[2][32][33];
    __shared__ unsigned AM[2][32][33];
    __shared__ unsigned BS[2][32][33];
    __shared__ int simH[2][32][32];

    int h = threadIdx.x >> 8;       // K-half
    int t = threadIdx.x & 255;
    int tx = t & 15;
    int ty = t >> 4;

    int acc[2][2] = {{0, 0}, {0, 0}};
    int accM[2] = {0, 0};

    int wlo = h * 128;
    for (int w0 = wlo; w0 < wlo + 128; w0 += 32) {
        if (src_est) {
            for (int e = t; e < 1024; e += 256) {
                int r = e >> 5;
                int c = e & 31;
                size_t src = ((size_t)(b0 + r) * FDIM + f) * WDIM + w0 + c;
                AS[h][c][r] = g_eS[src];
                AM[h][c][r] = g_eM[src];
            }
        } else {
            for (int e = t; e < 1024; e += 256) {
                int r = e >> 5;
                int c = e & 31;
                int b = b0 + r;
                int w = w0 + c;
                size_t base = ((size_t)b * FDIM) * WDIM + w;
                unsigned so1 = g_eS[base + (size_t)f1 * WDIM];
                unsigned so2 = g_eS[base + (size_t)f2 * WDIM];
                unsigned so3 = g_eS[base + (size_t)f3 * WDIM];
                unsigned mo1 = g_eM[base + (size_t)f1 * WDIM];
                unsigned mo2 = g_eM[base + (size_t)f2 * WDIM];
                unsigned mo3 = g_eM[base + (size_t)f3 * WDIM];
                unsigned Mf = mo1 & mo2 & mo3;
                unsigned Sf = (g_iS[(size_t)b * WDIM + w] ^ so1 ^ so2 ^ so3) & Mf;
                AS[h][c][r] = Sf;
                AM[h][c][r] = Mf;
            }
        }
        for (int e = t; e < 1024; e += 256) {
            int w = e >> 5;
            int m = e & 31;
            BS[h][w][m] = g_cbSt[((size_t)f * WDIM + w0 + w) * MDIM + m0 + m];
        }
        __syncthreads();
        #pragma unroll
        for (int w = 0; w < 32; w++) {
            unsigned sa0 = AS[h][w][tx * 2 + 0];
            unsigned sa1 = AS[h][w][tx * 2 + 1];
            unsigned ma0 = AM[h][w][tx * 2 + 0];
            unsigned ma1 = AM[h][w][tx * 2 + 1];
            unsigned sb0 = BS[h][w][ty * 2 + 0];
            unsigned sb1 = BS[h][w][ty * 2 + 1];
            accM[0] += __popc(ma0);
            accM[1] += __popc(ma1);
            acc[0][0] += __popc((sa0 ^ sb0) & ma0);
            acc[0][1] += __popc((sa0 ^ sb1) & ma0);
            acc[1][0] += __popc((sa1 ^ sb0) & ma1);
            acc[1][1] += __popc((sa1 ^ sb1) & ma1);
        }
        __syncthreads();
    }

    // per-half integer sims -> smem
    #pragma unroll
    for (int i = 0; i < 2; i++)
        #pragma unroll
        for (int j = 0; j < 2; j++)
            simH[h][tx * 2 + i][ty * 2 + j] = accM[i] - 2 * acc[i][j];
    __syncthreads();

    if (h == 0) {
        #pragma unroll
        for (int i = 0; i < 2; i++) {
            int b = b0 + tx * 2 + i;
            size_t base = ((size_t)b * FDIM + f) * 512;
            #pragma unroll
            for (int j = 0; j < 2; j++) {
                int m = m0 + ty * 2 + j;
                int sim = simH[0][tx * 2 + i][ty * 2 + j] + simH[1][tx * 2 + i][ty * 2 + j];
                if (src_est) {
                    g_sim[((size_t)b * FDIM + f) * MDIM + m] = (float)sim;
                } else {
                    int hi = (sim + 64) >> 7;        // hi in [-64,64]
                    int lo = sim - (hi << 7);        // lo in [-64,63]
                    g_simB[base + m] = __float2bfloat16((float)lo);
                    g_simB[base + 256 + m] = __float2bfloat16((float)(hi << 7));
                }
            }
        }
    }
}

// ---------------------------------------------------------------------------
// iteration GEMM2 via bf16 mma.sync.m16n8k16 (K=512 fused lo|hi planes from
// g_simB).  Block: 128 b x 64 d, f fixed.  grid (128, 2, F), 256 thr.
// Exact: lo, 128*hi exact bf16; f32 accumulation of ints < 2^21 exact.
// ---------------------------------------------------------------------------
__device__ __forceinline__ void hmma16816(float& c0, float& c1, float& c2, float& c3,
                                          unsigned a0, unsigned a1, unsigned a2, unsigned a3,
                                          unsigned b0, unsigned b1) {
    asm volatile(
        "mma.sync.aligned.m16n8k16.row.col.f32.bf16.bf16.f32 "
        "{%0,%1,%2,%3}, {%4,%5,%6,%7}, {%8,%9}, {%0,%1,%2,%3};\n"
        : "+f"(c0), "+f"(c1), "+f"(c2), "+f"(c3)
        : "r"(a0), "r"(a1), "r"(a2), "r"(a3), "r"(b0), "r"(b1));
}

__global__ void gemm2_bf16_kernel() {
    if (g_done) return;
    __shared__ __align__(16) unsigned sA[128 * 36];   // 128 rows x (32 data + 4 pad)
    __shared__ __align__(16) unsigned sB[64 * 36];
    __shared__ unsigned char sSM[128][64];

    int f = blockIdx.z;
    int d0 = blockIdx.x * 64;
    int b0 = blockIdx.y * 128;
    int tid = threadIdx.x;
    int wid = tid >> 5;
    int lane = tid & 31;
    int g = lane >> 2;
    int tig = lane & 3;
    int wb = wid & 3;     // 32 b-rows
    int wd = wid >> 2;    // 0..1: 32 d-cols

    float acc[2][4][4];
    #pragma unroll
    for (int mt = 0; mt < 2; mt++)
        #pragma unroll
        for (int nt = 0; nt < 4; nt++)
            #pragma unroll
            for (int i = 0; i < 4; i++) acc[mt][nt][i] = 0.f;

    const uint4* A4 = (const uint4*)g_simB;   // 64 uint4 per (b,f) row
    const uint4* B4 = (const uint4*)g_cbB;    // 32 uint4 per (f,d) row
    uint4* sA4 = (uint4*)sA;                  // row stride 9 uint4
    uint4* sB4 = (uint4*)sB;

    for (int kc = 0; kc < 8; kc++) {
        for (int i = tid; i < 1024; i += 256) {
            int row = i >> 3;
            int un = i & 7;
            sA4[row * 9 + un] = A4[((size_t)(b0 + row) * FDIM + f) * 64 + kc * 8 + un];
        }
        for (int i = tid; i < 512; i += 256) {
            int row = i >> 3;
            int un = i & 7;
            sB4[row * 9 + un] = B4[((size_t)f * DDIM + d0 + row) * 32 + (kc & 3) * 8 + un];
        }
        __syncthreads();
        #pragma unroll
        for (int s = 0; s < 4; s++) {
            unsigned a[2][4];
            #pragma unroll
            for (int mt = 0; mt < 2; mt++) {
                int r = wb * 32 + mt * 16 + g;
                a[mt][0] = sA[r * 36 + s * 8 + tig];
                a[mt][1] = sA[(r + 8) * 36 + s * 8 + tig];
                a[mt][2] = sA[r * 36 + s * 8 + tig + 4];
                a[mt][3] = sA[(r + 8) * 36 + s * 8 + tig + 4];
            }
            #pragma unroll
            for (int nt = 0; nt < 4; nt++) {
                int rd = wd * 32 + nt * 8 + g;
                unsigned bb0 = sB[rd * 36 + s * 8 + tig];
                unsigned bb1 = sB[rd * 36 + s * 8 + tig + 4];
                #pragma unroll
                for (int mt = 0; mt < 2; mt++)
                    hmma16816(acc[mt][nt][0], acc[mt][nt][1], acc[mt][nt][2], acc[mt][nt][3],
                              a[mt][0], a[mt][1], a[mt][2], a[mt][3], bb0, bb1);
            }
        }
        __syncthreads();
    }

    #pragma unroll
    for (int mt = 0; mt < 2; mt++) {
        int r0 = wb * 32 + mt * 16 + g;
        #pragma unroll
        for (int nt = 0; nt < 4; nt++) {
            int c0 = wd * 32 + nt * 8 + tig * 2;
            float v0 = acc[mt][nt][0];
            float v1 = acc[mt][nt][1];
            float v2 = acc[mt][nt][2];
            float v3 = acc[mt][nt][3];
            sSM[r0][c0]         = (unsigned char)((v0 < 0.f ? 1u : 0u) | (v0 != 0.f ? 2u : 0u));
            sSM[r0][c0 + 1]     = (unsigned char)((v1 < 0.f ? 1u : 0u) | (v1 != 0.f ? 2u : 0u));
            sSM[r0 + 8][c0]     = (unsigned char)((v2 < 0.f ? 1u : 0u) | (v2 != 0.f ? 2u : 0u));
            sSM[r0 + 8][c0 + 1] = (unsigned char)((v3 < 0.f ? 1u : 0u) | (v3 != 0.f ? 2u : 0u));
        }
    }
    __syncthreads();

    int ldiff = 0;
    {
        int row = tid >> 1;
        int wsel = tid & 1;
        unsigned ws = 0, wm = 0;
        #pragma unroll
        for (int n = 0; n < 32; n++) {
            unsigned byte = sSM[row][wsel * 32 + n];
            ws |= (byte & 1u) << n;
            wm |= ((byte >> 1) & 1u) << n;
        }
        size_t o = ((size_t)(b0 + row) * FDIM + f) * WDIM + (d0 >> 5) + wsel;
        if (ws != g_eS[o] || wm != g_eM[o]) ldiff = 1;
        g_eS[o] = ws;
        g_eM[o] = wm;
    }
    last_block_step(ldiff, 1024);
}

// ---------------------------------------------------------------------------
// argmax over m (first-index tie-break) + write k.  Output dtype: float32.
// ---------------------------------------------------------------------------
__global__ void argmax_kernel(float* __restrict__ out, int out_size) {
    int gtid = blockIdx.x * blockDim.x + threadIdx.x;
    int w = gtid >> 5;
    int lane = gtid & 31;
    if (w < BDIM * FDIM) {
        const float* srow = g_sim + (size_t)w * MDIM;
        float bv = -3.0e38f;
        int bi = 0;
        for (int m = lane; m < MDIM; m += 32) {
            float v = srow[m];
            if (v > bv) { bv = v; bi = m; }
        }
        for (int off = 16; off > 0; off >>= 1) {
            float ov = __shfl_down_sync(0xffffffffu, bv, off);
            int oi = __shfl_down_sync(0xffffffffu, bi, off);
            if (ov > bv || (ov == bv && oi < bi)) { bv = ov; bi = oi; }
        }
        if (lane == 0) out[w] = (float)bi;
    }
    if (gtid == 0 && out_size > BDIM * FDIM) out[BDIM * FDIM] = (float)g_k;
}

// ---------------------------------------------------------------------------
extern "C" void kernel_launch(void* const* d_in, const int* in_sizes, int n_in,
                              void* d_out, int out_size) {
    const float* inp;
    const float* cb;
    if (in_sizes[0] < in_sizes[1]) { inp = (const float*)d_in[0]; cb = (const float*)d_in[1]; }
    else                           { inp = (const float*)d_in[1]; cb = (const float*)d_in[0]; }
    float* out = (float*)d_out;

    // launch #0..#3: setup, g1f32, g2f32, g1packed (ncu capture = index 3)
    setup_kernel<<<42016, 256>>>(cb, inp);
    gemm1_f32_kernel<<<dim3(16, FDIM, 16), 256>>>(cb, inp);
    gemm2_f32_kernel<<<dim3(DDIM / 64, BDIM / 64, FDIM), 256>>>(cb);

    for (int it = 1; it < NITERS; it++) {
        gemm1_packed_kernel<<<dim3(BDIM / 32, MDIM / 32, FDIM), 512>>>(0, 1);
        gemm2_bf16_kernel<<<dim3(DDIM / 64, BDIM / 128, FDIM), 256>>>();
    }

    gemm1_packed_kernel<<<dim3(BDIM / 32, MDIM / 32, FDIM), 512>>>(1, 0);
    argmax_kernel<<<(BDIM * FDIM * 32) / 256, 256>>>(out, out_size);
}